// round 1
// baseline (speedup 1.0000x reference)
#include <cuda_runtime.h>

// ---------------- problem constants (from reference) ----------------
#define NND   50000      // num nodes
#define DEG   16         // in-degree (dst = repeat(arange(N), DEG) -> contiguous segments)
#define NE    (NND*DEG)
#define IN_F  128
#define HID   64
#define NH    4
#define BATCH 64

// ---------------- scratch (no cudaMalloc allowed) ----------------
__device__ float g_f1 [NND*NH*HID];   // [N,4,64]  pre-bias features, layer 1
__device__ float g_el1[NND*NH];
__device__ float g_er1[NND*NH];
__device__ float g_h1 [NND*NH*HID];   // relu(agg1 + b1) -> layer-2 input [N,256]
__device__ float g_f2 [NND*HID];      // [N,64]
__device__ float g_el2[NND];
__device__ float g_er2[NND];
__device__ float g_h2 [NND*HID];      // [N,64]
__device__ float g_loss[BATCH];

// ---------------- register-blocked GEMM with optional row gather ----------------
// C[m, n] = sum_k A[gidx[m], k] * B[k, n]
template<int BM, int BN, int BK, int TM, int TN>
__global__ __launch_bounds__((BM/TM)*(BN/TN))
void gemm_gather(const float* __restrict__ A, const int* __restrict__ gidx,
                 const float* __restrict__ B, float* __restrict__ C,
                 int M, int K, int Ncols) {
    __shared__ float As[BK][BM];
    __shared__ float Bs[BK][BN];
    constexpr int NT = (BM/TM)*(BN/TN);
    const int tid = threadIdx.x;
    const int tx  = tid % (BN/TN);
    const int ty  = tid / (BN/TN);
    const int m0  = blockIdx.x * BM;
    const int n0  = blockIdx.y * BN;

    float acc[TM][TN];
    #pragma unroll
    for (int i = 0; i < TM; i++)
        #pragma unroll
        for (int j = 0; j < TN; j++) acc[i][j] = 0.f;

    for (int k0 = 0; k0 < K; k0 += BK) {
        #pragma unroll
        for (int e = tid; e < BM*BK; e += NT) {
            int m = e / BK, k = e % BK;
            float v = 0.f;
            int gm = m0 + m;
            if (gm < M) {
                int row = gidx ? gidx[gm] : gm;
                v = A[(long)row * K + k0 + k];
            }
            As[k][m] = v;
        }
        #pragma unroll
        for (int e = tid; e < BK*BN; e += NT) {
            int k = e / BN, n = e % BN;
            Bs[k][n] = B[(long)(k0 + k) * Ncols + n0 + n];
        }
        __syncthreads();
        #pragma unroll
        for (int k = 0; k < BK; k++) {
            float ra[TM], rb[TN];
            #pragma unroll
            for (int i = 0; i < TM; i++) ra[i] = As[k][ty*TM + i];
            #pragma unroll
            for (int j = 0; j < TN; j++) rb[j] = Bs[k][tx*TN + j];
            #pragma unroll
            for (int i = 0; i < TM; i++)
                #pragma unroll
                for (int j = 0; j < TN; j++) acc[i][j] += ra[i] * rb[j];
        }
        __syncthreads();
    }

    #pragma unroll
    for (int i = 0; i < TM; i++) {
        int gm = m0 + ty*TM + i;
        if (gm >= M) break;
        #pragma unroll
        for (int j = 0; j < TN; j++)
            C[(long)gm * Ncols + n0 + tx*TN + j] = acc[i][j];
    }
}

// ---------------- el/er attention dots: one warp per (node, head) ----------------
__global__ void dots_kernel(const float* __restrict__ f, const float* __restrict__ al,
                            const float* __restrict__ ar, float* __restrict__ el,
                            float* __restrict__ er, int nh) {
    int wid  = (blockIdx.x * blockDim.x + threadIdx.x) >> 5;
    int lane = threadIdx.x & 31;
    if (wid >= NND * nh) return;
    int h = wid % nh;
    const float* fr = f + (long)wid * HID;
    float x0 = fr[lane], x1 = fr[lane + 32];
    float sl = x0 * al[h*HID + lane] + x1 * al[h*HID + lane + 32];
    float sr = x0 * ar[h*HID + lane] + x1 * ar[h*HID + lane + 32];
    #pragma unroll
    for (int o = 16; o > 0; o >>= 1) {
        sl += __shfl_xor_sync(~0u, sl, o);
        sr += __shfl_xor_sync(~0u, sr, o);
    }
    if (lane == 0) { el[wid] = sl; er[wid] = sr; }
}

// ---------------- segment-softmax + weighted aggregation ----------------
// One warp per (node, head). Edges for node v are contiguous: [v*DEG, v*DEG+DEG).
__global__ void agg_kernel(const float* __restrict__ f, const float* __restrict__ el,
                           const float* __restrict__ er, const float* __restrict__ bias,
                           const int* __restrict__ src, float* __restrict__ out,
                           int nh, int do_relu) {
    int gw   = (blockIdx.x * blockDim.x + threadIdx.x) >> 5;
    int lane = threadIdx.x & 31;
    if (gw >= NND * nh) return;
    int v = gw / nh, h = gw % nh;

    float erv = er[(long)v * nh + h];
    int   s   = 0;
    float e   = -1e30f;
    if (lane < DEG) {
        s = src[v * DEG + lane];
        float x = el[(long)s * nh + h] + erv;
        e = x > 0.f ? x : 0.2f * x;           // leaky_relu(0.2)
    }
    // segment softmax over 16 lanes
    float m = e;
    #pragma unroll
    for (int o = 8; o > 0; o >>= 1) m = fmaxf(m, __shfl_xor_sync(~0u, m, o, 16));
    float ex = (lane < DEG) ? __expf(e - m) : 0.f;
    float sm = ex;
    #pragma unroll
    for (int o = 8; o > 0; o >>= 1) sm += __shfl_xor_sync(~0u, sm, o, 16);
    float alpha = ex / sm;                    // valid on lanes < DEG

    // weighted gather-sum: 2 dims per lane
    float2 acc = make_float2(0.f, 0.f);
    #pragma unroll
    for (int j = 0; j < DEG; j++) {
        int   sj = __shfl_sync(~0u, s, j);
        float aj = __shfl_sync(~0u, alpha, j);
        float2 val = *reinterpret_cast<const float2*>(
            &f[((long)sj * nh + h) * HID + lane * 2]);
        acc.x += aj * val.x;
        acc.y += aj * val.y;
    }
    int d = lane * 2;
    float o0 = acc.x + bias[h*HID + d];
    float o1 = acc.y + bias[h*HID + d + 1];
    if (do_relu) { o0 = fmaxf(o0, 0.f); o1 = fmaxf(o1, 0.f); }
    out[((long)v * nh + h) * HID + d]     = o0;
    out[((long)v * nh + h) * HID + d + 1] = o1;
}

// ---------------- scores, labels, per-row loss ----------------
__global__ void score_kernel(const float* __restrict__ h2, const int* __restrict__ uid,
                             const int* __restrict__ iid, float* __restrict__ out) {
    int i = blockIdx.x;     // row 0..63
    int d = threadIdx.x;    // col 0..63
    float su = h2[(long)uid[i] * HID + d];
    float si = h2[(long)iid[i] * HID + d];
    float sc = su * si;
    out[1 + i*BATCH + d] = sc;                          // scores
    out[1 + BATCH*BATCH + i*BATCH + d] = (i == d) ? 1.f : 0.f;  // labels (eye)

    __shared__ float buf[BATCH];
    __shared__ float diag;
    if (d == i) diag = sc;
    buf[d] = sc;
    __syncthreads();
    for (int st = 32; st > 0; st >>= 1) {
        if (d < st) buf[d] = fmaxf(buf[d], buf[d + st]);
        __syncthreads();
    }
    float mx = buf[0];
    __syncthreads();
    buf[d] = expf(sc - mx);
    __syncthreads();
    for (int st = 32; st > 0; st >>= 1) {
        if (d < st) buf[d] += buf[d + st];
        __syncthreads();
    }
    if (d == 0) {
        float lse = mx + logf(buf[0]);
        g_loss[i] = lse - diag;   // -log_softmax(scores)[i,i]
    }
}

__global__ void finalize_kernel(float* __restrict__ out) {
    if (threadIdx.x == 0) {
        float s = 0.f;
        for (int i = 0; i < BATCH; i++) s += g_loss[i];
        out[0] = s / (float)BATCH;
    }
}

// ---------------- launcher ----------------
extern "C" void kernel_launch(void* const* d_in, const int* in_sizes, int n_in,
                              void* d_out, int out_size) {
    const int*   feat_ids = (const int*)  d_in[0];
    const int*   src      = (const int*)  d_in[1];
    /* dst = d_in[2] is repeat(arange(N), DEG) by construction -> implicit */
    const int*   user_ids = (const int*)  d_in[3];
    const int*   item_ids = (const int*)  d_in[4];
    const float* emb      = (const float*)d_in[5];
    const float* W1       = (const float*)d_in[6];
    const float* a_l1     = (const float*)d_in[7];
    const float* a_r1     = (const float*)d_in[8];
    const float* b1       = (const float*)d_in[9];
    const float* W2       = (const float*)d_in[10];
    const float* a_l2     = (const float*)d_in[11];
    const float* a_r2     = (const float*)d_in[12];
    const float* b2       = (const float*)d_in[13];
    float* out = (float*)d_out;

    float *f1, *el1, *er1, *h1, *f2, *el2, *er2, *h2;
    cudaGetSymbolAddress((void**)&f1,  g_f1);
    cudaGetSymbolAddress((void**)&el1, g_el1);
    cudaGetSymbolAddress((void**)&er1, g_er1);
    cudaGetSymbolAddress((void**)&h1,  g_h1);
    cudaGetSymbolAddress((void**)&f2,  g_f2);
    cudaGetSymbolAddress((void**)&el2, g_el2);
    cudaGetSymbolAddress((void**)&er2, g_er2);
    cudaGetSymbolAddress((void**)&h2,  g_h2);

    const int MB = (NND + 127) / 128;   // 391

    // layer 1: f1 = emb[feat_ids] @ W1   (50000 x 128 x 256)
    gemm_gather<128,128,8,8,8><<<dim3(MB, 2), 256>>>(emb, feat_ids, W1, f1,
                                                     NND, IN_F, NH*HID);
    // el1/er1 : one warp per (node, head)
    dots_kernel<<<(NND*NH)/8, 256>>>(f1, a_l1, a_r1, el1, er1, NH);
    // agg + bias + relu -> h1
    agg_kernel<<<(NND*NH)/8, 256>>>(f1, el1, er1, b1, src, h1, NH, 1);

    // layer 2: f2 = h1 @ W2   (50000 x 256 x 64)
    gemm_gather<128,64,8,8,4><<<dim3(MB, 1), 256>>>(h1, nullptr, W2, f2,
                                                    NND, NH*HID, HID);
    dots_kernel<<<NND/8, 256>>>(f2, a_l2, a_r2, el2, er2, 1);
    agg_kernel<<<NND/8, 256>>>(f2, el2, er2, b2, src, h2, 1, 0);

    // scores / labels / loss
    score_kernel<<<BATCH, BATCH>>>(h2, user_ids, item_ids, out);
    finalize_kernel<<<1, 32>>>(out);
}

// round 2
// speedup vs baseline: 1.2856x; 1.2856x over previous
#include <cuda_runtime.h>

// ---------------- problem constants ----------------
#define NND   50000
#define DEG   16
#define IN_F  128
#define HID   64
#define NH    4
#define BATCH 64

// ---------------- scratch ----------------
__device__ float g_f1 [NND*NH*HID];
__device__ float g_el1[NND*NH];
__device__ float g_er1[NND*NH];
__device__ float g_h1 [NND*NH*HID];
__device__ float g_f2 [NND*HID];
__device__ float g_el2[NND];
__device__ float g_er2[NND];
__device__ float g_h2 [NND*HID];
__device__ float g_loss[BATCH];

// ---------------- GEMM (full-width N) with fused attention dots ----------------
// C[m, 0:BN] = A[gidx[m], :] @ B    ;  el/er[m,h] = dot(C[m, h*64:(h+1)*64], a_{l,r}[h])
// Requires: Ncols == BN == NHh*64, TN == 8.
template<int BM,int BN,int BK,int TM,int TN,int NHh>
__global__ __launch_bounds__((BM/TM)*(BN/TN))
void gemm_fused(const float* __restrict__ A, const int* __restrict__ gidx,
                const float* __restrict__ B,
                const float* __restrict__ al, const float* __restrict__ ar,
                float* __restrict__ C, float* __restrict__ el, float* __restrict__ er,
                int M, int K) {
    constexpr int NT = (BM/TM)*(BN/TN);
    __shared__ float As[BK][BM];
    __shared__ float Bs[BK][BN];
    const int tid = threadIdx.x;
    const int tx  = tid % (BN/TN);
    const int ty  = tid / (BN/TN);
    const int m0  = blockIdx.x * BM;

    // hoist per-thread A row bases (gather once)
    constexpr int A_F4 = BM*BK/4;
    constexpr int A_IT = A_F4 / NT;
    static_assert(A_IT >= 1 && A_F4 % NT == 0, "A tiling");
    long arow[A_IT];
    #pragma unroll
    for (int r = 0; r < A_IT; r++) {
        int idx = tid + r*NT;
        int mA  = idx / (BK/4);
        int gm  = m0 + mA;
        int row = (gm < M) ? (gidx ? gidx[gm] : gm) : 0;
        arow[r] = (long)row * K;
    }
    constexpr int B_F4 = BK*BN/4;
    constexpr int B_IT = B_F4 / NT;
    static_assert(B_IT >= 1 && B_F4 % NT == 0, "B tiling");

    float acc[TM][TN];
    #pragma unroll
    for (int i = 0; i < TM; i++)
        #pragma unroll
        for (int j = 0; j < TN; j++) acc[i][j] = 0.f;

    for (int k0 = 0; k0 < K; k0 += BK) {
        #pragma unroll
        for (int r = 0; r < A_IT; r++) {
            int idx = tid + r*NT;
            int mA  = idx / (BK/4);
            int kq  = idx % (BK/4);
            float4 v = *reinterpret_cast<const float4*>(A + arow[r] + k0 + kq*4);
            As[kq*4+0][mA] = v.x;
            As[kq*4+1][mA] = v.y;
            As[kq*4+2][mA] = v.z;
            As[kq*4+3][mA] = v.w;
        }
        #pragma unroll
        for (int r = 0; r < B_IT; r++) {
            int idx = tid + r*NT;
            int kB  = idx / (BN/4);
            int nq  = idx % (BN/4);
            float4 v = *reinterpret_cast<const float4*>(B + (long)(k0+kB)*BN + nq*4);
            *reinterpret_cast<float4*>(&Bs[kB][nq*4]) = v;
        }
        __syncthreads();
        #pragma unroll
        for (int k = 0; k < BK; k++) {
            float ra[TM], rb[TN];
            #pragma unroll
            for (int i = 0; i < TM; i++) ra[i] = As[k][ty*TM + i];
            #pragma unroll
            for (int j = 0; j < TN; j++) rb[j] = Bs[k][tx*TN + j];
            #pragma unroll
            for (int i = 0; i < TM; i++)
                #pragma unroll
                for (int j = 0; j < TN; j++) acc[i][j] += ra[i] * rb[j];
        }
        __syncthreads();
    }

    // epilogue: store C rows + fused el/er head dots (8 lanes per head)
    float alr[TN], arr[TN];
    #pragma unroll
    for (int j = 0; j < TN; j++) { int n = tx*TN + j; alr[j] = al[n]; arr[j] = ar[n]; }

    #pragma unroll
    for (int i = 0; i < TM; i++) {
        int gm = m0 + ty*TM + i;
        float sl = 0.f, sr = 0.f;
        #pragma unroll
        for (int j = 0; j < TN; j++) { sl += acc[i][j]*alr[j]; sr += acc[i][j]*arr[j]; }
        #pragma unroll
        for (int o = 1; o < 8; o <<= 1) {
            sl += __shfl_xor_sync(~0u, sl, o);
            sr += __shfl_xor_sync(~0u, sr, o);
        }
        if (gm < M) {
            #pragma unroll
            for (int j = 0; j < TN; j += 4)
                *reinterpret_cast<float4*>(&C[(long)gm*BN + tx*TN + j]) =
                    make_float4(acc[i][j], acc[i][j+1], acc[i][j+2], acc[i][j+3]);
            if ((tx & 7) == 0) {
                int h = tx >> 3;
                el[(long)gm*NHh + h] = sl;
                er[(long)gm*NHh + h] = sr;
            }
        }
    }
}

// ---------------- segment-softmax + weighted aggregation ----------------
__global__ void agg_kernel(const float* __restrict__ f, const float* __restrict__ el,
                           const float* __restrict__ er, const float* __restrict__ bias,
                           const int* __restrict__ src, float* __restrict__ out,
                           int nh, int do_relu) {
    int gw   = (blockIdx.x * blockDim.x + threadIdx.x) >> 5;
    int lane = threadIdx.x & 31;
    if (gw >= NND * nh) return;
    int v = gw / nh, h = gw % nh;

    float erv = er[(long)v * nh + h];
    int   s   = 0;
    float e   = -1e30f;
    if (lane < DEG) {
        s = src[v * DEG + lane];
        float x = el[(long)s * nh + h] + erv;
        e = x > 0.f ? x : 0.2f * x;   // leaky_relu
    }
    float m = e;
    #pragma unroll
    for (int o = 8; o > 0; o >>= 1) m = fmaxf(m, __shfl_xor_sync(~0u, m, o, 16));
    float ex = (lane < DEG) ? __expf(e - m) : 0.f;
    float sm = ex;
    #pragma unroll
    for (int o = 8; o > 0; o >>= 1) sm += __shfl_xor_sync(~0u, sm, o, 16);
    float alpha = ex / sm;

    float2 acc = make_float2(0.f, 0.f);
    #pragma unroll
    for (int j = 0; j < DEG; j++) {
        int   sj = __shfl_sync(~0u, s, j);
        float aj = __shfl_sync(~0u, alpha, j);
        float2 val = *reinterpret_cast<const float2*>(
            &f[((long)sj * nh + h) * HID + lane * 2]);
        acc.x += aj * val.x;
        acc.y += aj * val.y;
    }
    int d = lane * 2;
    float o0 = acc.x + bias[h*HID + d];
    float o1 = acc.y + bias[h*HID + d + 1];
    if (do_relu) { o0 = fmaxf(o0, 0.f); o1 = fmaxf(o1, 0.f); }
    out[((long)v * nh + h) * HID + d]     = o0;
    out[((long)v * nh + h) * HID + d + 1] = o1;
}

// ---------------- scores, labels, per-row loss ----------------
__global__ void score_kernel(const float* __restrict__ h2, const int* __restrict__ uid,
                             const int* __restrict__ iid, float* __restrict__ out) {
    int i = blockIdx.x;
    int d = threadIdx.x;
    float su = h2[(long)uid[i] * HID + d];
    float si = h2[(long)iid[i] * HID + d];
    float sc = su * si;
    out[1 + i*BATCH + d] = sc;
    out[1 + BATCH*BATCH + i*BATCH + d] = (i == d) ? 1.f : 0.f;

    __shared__ float buf[BATCH];
    __shared__ float diag;
    if (d == i) diag = sc;
    buf[d] = sc;
    __syncthreads();
    for (int st = 32; st > 0; st >>= 1) {
        if (d < st) buf[d] = fmaxf(buf[d], buf[d + st]);
        __syncthreads();
    }
    float mx = buf[0];
    __syncthreads();
    buf[d] = expf(sc - mx);
    __syncthreads();
    for (int st = 32; st > 0; st >>= 1) {
        if (d < st) buf[d] += buf[d + st];
        __syncthreads();
    }
    if (d == 0) {
        float lse = mx + logf(buf[0]);
        g_loss[i] = lse - diag;
    }
}

__global__ void finalize_kernel(float* __restrict__ out) {
    if (threadIdx.x == 0) {
        float s = 0.f;
        for (int i = 0; i < BATCH; i++) s += g_loss[i];
        out[0] = s / (float)BATCH;
    }
}

// ---------------- launcher ----------------
extern "C" void kernel_launch(void* const* d_in, const int* in_sizes, int n_in,
                              void* d_out, int out_size) {
    const int*   feat_ids = (const int*)  d_in[0];
    const int*   src      = (const int*)  d_in[1];
    const int*   user_ids = (const int*)  d_in[3];
    const int*   item_ids = (const int*)  d_in[4];
    const float* emb      = (const float*)d_in[5];
    const float* W1       = (const float*)d_in[6];
    const float* a_l1     = (const float*)d_in[7];
    const float* a_r1     = (const float*)d_in[8];
    const float* b1       = (const float*)d_in[9];
    const float* W2       = (const float*)d_in[10];
    const float* a_l2     = (const float*)d_in[11];
    const float* a_r2     = (const float*)d_in[12];
    const float* b2       = (const float*)d_in[13];
    float* out = (float*)d_out;

    float *f1, *el1, *er1, *h1, *f2, *el2, *er2, *h2;
    cudaGetSymbolAddress((void**)&f1,  g_f1);
    cudaGetSymbolAddress((void**)&el1, g_el1);
    cudaGetSymbolAddress((void**)&er1, g_er1);
    cudaGetSymbolAddress((void**)&h1,  g_h1);
    cudaGetSymbolAddress((void**)&f2,  g_f2);
    cudaGetSymbolAddress((void**)&el2, g_el2);
    cudaGetSymbolAddress((void**)&er2, g_er2);
    cudaGetSymbolAddress((void**)&h2,  g_h2);

    // layer 1: f1 = emb[feat_ids] @ W1 (50000x128x256) + fused el1/er1
    gemm_fused<64,256,16,8,8,4><<<(NND+63)/64, 256>>>(
        emb, feat_ids, W1, a_l1, a_r1, f1, el1, er1, NND, IN_F);
    agg_kernel<<<(NND*NH)/8, 256>>>(f1, el1, er1, b1, src, h1, NH, 1);

    // layer 2: f2 = h1 @ W2 (50000x256x64) + fused el2/er2
    gemm_fused<128,64,32,8,8,1><<<(NND+127)/128, 128>>>(
        h1, nullptr, W2, a_l2, a_r2, f2, el2, er2, NND, NH*HID);
    agg_kernel<<<NND/8, 256>>>(f2, el2, er2, b2, src, h2, 1, 0);

    score_kernel<<<BATCH, BATCH>>>(h2, user_ids, item_ids, out);
    finalize_kernel<<<1, 32>>>(out);
}

// round 3
// speedup vs baseline: 1.4186x; 1.1034x over previous
#include <cuda_runtime.h>

// ---------------- problem constants ----------------
#define NND   50000
#define DEG   16
#define IN_F  128
#define HID   64
#define NH    4
#define BATCH 64

typedef unsigned long long ull;

// ---------------- scratch ----------------
__device__ float g_f1 [NND*NH*HID];
__device__ float g_el1[NND*NH];
__device__ float g_er1[NND*NH];
__device__ float g_h1 [NND*NH*HID];
__device__ float g_f2 [NND*HID];
__device__ float g_el2[NND];
__device__ float g_er2[NND];
__device__ float g_h2 [NND*HID];
__device__ float g_loss[BATCH];

// ---------------- packed f32x2 helpers (sm_103a FFMA2 pipe) ----------------
__device__ __forceinline__ ull pack_dup(float x) {
    ull r; asm("mov.b64 %0, {%1, %1};" : "=l"(r) : "f"(x)); return r;
}
__device__ __forceinline__ void ffma2(ull& acc, ull a, ull b) {
    asm("fma.rn.f32x2 %0, %1, %2, %0;" : "+l"(acc) : "l"(a), "l"(b));
}
__device__ __forceinline__ float2 unpack2(ull v) {
    float2 f; asm("mov.b64 {%0, %1}, %2;" : "=f"(f.x), "=f"(f.y) : "l"(v)); return f;
}

// ---------------- GEMM (full-width N) with fused attention dots, FFMA2 core ----
// C[m, 0:BN] = A[gidx[m], :] @ B ; el/er[m,h] = dot(C[m, h*64:(h+1)*64], a_{l,r}[h])
template<int BM,int BN,int BK,int TM,int TN,int NHh>
__global__ __launch_bounds__((BM/TM)*(BN/TN))
void gemm_fused(const float* __restrict__ A, const int* __restrict__ gidx,
                const float* __restrict__ B,
                const float* __restrict__ al, const float* __restrict__ ar,
                float* __restrict__ C, float* __restrict__ el, float* __restrict__ er,
                int M, int K) {
    constexpr int NT = (BM/TM)*(BN/TN);
    __shared__ float As[BK][BM];
    __shared__ float Bs[BK][BN];
    const int tid = threadIdx.x;
    const int tx  = tid % (BN/TN);
    const int ty  = tid / (BN/TN);
    const int m0  = blockIdx.x * BM;

    constexpr int A_F4 = BM*BK/4;
    constexpr int A_IT = A_F4 / NT;
    static_assert(A_IT >= 1 && A_F4 % NT == 0, "A tiling");
    long arow[A_IT];
    #pragma unroll
    for (int r = 0; r < A_IT; r++) {
        int idx = tid + r*NT;
        int mA  = idx / (BK/4);
        int gm  = m0 + mA;
        int row = (gm < M) ? (gidx ? gidx[gm] : gm) : 0;
        arow[r] = (long)row * K;
    }
    constexpr int B_F4 = BK*BN/4;
    constexpr int B_IT = B_F4 / NT;
    static_assert(B_IT >= 1 && B_F4 % NT == 0, "B tiling");

    // accumulators: pairs along M (rows 2*i2, 2*i2+1)
    ull acc2[TM/2][TN];
    #pragma unroll
    for (int i = 0; i < TM/2; i++)
        #pragma unroll
        for (int j = 0; j < TN; j++) acc2[i][j] = 0ull;

    for (int k0 = 0; k0 < K; k0 += BK) {
        #pragma unroll
        for (int r = 0; r < A_IT; r++) {
            int idx = tid + r*NT;
            int mA  = idx / (BK/4);
            int kq  = idx % (BK/4);
            float4 v = *reinterpret_cast<const float4*>(A + arow[r] + k0 + kq*4);
            As[kq*4+0][mA] = v.x;
            As[kq*4+1][mA] = v.y;
            As[kq*4+2][mA] = v.z;
            As[kq*4+3][mA] = v.w;
        }
        #pragma unroll
        for (int r = 0; r < B_IT; r++) {
            int idx = tid + r*NT;
            int kB  = idx / (BN/4);
            int nq  = idx % (BN/4);
            float4 v = *reinterpret_cast<const float4*>(B + (long)(k0+kB)*BN + nq*4);
            *reinterpret_cast<float4*>(&Bs[kB][nq*4]) = v;
        }
        __syncthreads();
        #pragma unroll
        for (int k = 0; k < BK; k++) {
            ull a2[TM/2];
            const ull* ap = reinterpret_cast<const ull*>(&As[k][ty*TM]);
            #pragma unroll
            for (int i = 0; i < TM/2; i++) a2[i] = ap[i];
            ull b2[TN];
            #pragma unroll
            for (int j = 0; j < TN; j++) b2[j] = pack_dup(Bs[k][tx*TN + j]);
            #pragma unroll
            for (int i = 0; i < TM/2; i++)
                #pragma unroll
                for (int j = 0; j < TN; j++) ffma2(acc2[i][j], a2[i], b2[j]);
        }
        __syncthreads();
    }

    // unpack to scalar view
    float acc[TM][TN];
    #pragma unroll
    for (int i = 0; i < TM/2; i++)
        #pragma unroll
        for (int j = 0; j < TN; j++) {
            float2 p = unpack2(acc2[i][j]);
            acc[2*i  ][j] = p.x;
            acc[2*i+1][j] = p.y;
        }

    // epilogue: store C rows + fused el/er head dots (8 lanes per head group)
    float alr[TN], arr[TN];
    #pragma unroll
    for (int j = 0; j < TN; j++) { int n = tx*TN + j; alr[j] = al[n]; arr[j] = ar[n]; }

    #pragma unroll
    for (int i = 0; i < TM; i++) {
        int gm = m0 + ty*TM + i;
        float sl = 0.f, sr = 0.f;
        #pragma unroll
        for (int j = 0; j < TN; j++) { sl += acc[i][j]*alr[j]; sr += acc[i][j]*arr[j]; }
        #pragma unroll
        for (int o = 1; o < 8; o <<= 1) {
            sl += __shfl_xor_sync(~0u, sl, o);
            sr += __shfl_xor_sync(~0u, sr, o);
        }
        if (gm < M) {
            #pragma unroll
            for (int j = 0; j < TN; j += 4)
                *reinterpret_cast<float4*>(&C[(long)gm*BN + tx*TN + j]) =
                    make_float4(acc[i][j], acc[i][j+1], acc[i][j+2], acc[i][j+3]);
            if ((tx & 7) == 0) {
                int h = tx >> 3;
                el[(long)gm*NHh + h] = sl;
                er[(long)gm*NHh + h] = sr;
            }
        }
    }
}

// ---------------- segment-softmax + weighted aggregation (2 edges/iter) -------
__global__ void agg_kernel(const float* __restrict__ f, const float* __restrict__ el,
                           const float* __restrict__ er, const float* __restrict__ bias,
                           const int* __restrict__ src, float* __restrict__ out,
                           int nh, int do_relu) {
    int gw   = (blockIdx.x * blockDim.x + threadIdx.x) >> 5;
    int lane = threadIdx.x & 31;
    if (gw >= NND * nh) return;
    int v = gw / nh, h = gw - v*nh;

    float erv = er[(long)v * nh + h];
    int   s   = 0;
    float e   = -1e30f;
    if (lane < DEG) {
        s = src[v * DEG + lane];
        float x = el[(long)s * nh + h] + erv;
        e = x > 0.f ? x : 0.2f * x;   // leaky_relu(0.2)
    }
    float m = e;
    #pragma unroll
    for (int o = 8; o > 0; o >>= 1) m = fmaxf(m, __shfl_xor_sync(~0u, m, o, 16));
    float ex = (lane < DEG) ? __expf(e - m) : 0.f;
    float sm = ex;
    #pragma unroll
    for (int o = 8; o > 0; o >>= 1) sm += __shfl_xor_sync(~0u, sm, o, 16);
    float alpha = ex / sm;            // valid on lanes 0..15

    // lanes 0..15 = dims [0..63] via float4, half=lane>>4 selects edge parity
    int half = lane >> 4;
    int dl   = lane & 15;
    float4 acc = make_float4(0.f, 0.f, 0.f, 0.f);
    #pragma unroll
    for (int j = 0; j < DEG/2; j++) {
        int   eidx = 2*j + half;
        int   sj = __shfl_sync(~0u, s,     eidx);
        float aj = __shfl_sync(~0u, alpha, eidx);
        float4 val = *reinterpret_cast<const float4*>(
            &f[((long)sj * nh + h) * HID + dl * 4]);
        acc.x += aj * val.x;
        acc.y += aj * val.y;
        acc.z += aj * val.z;
        acc.w += aj * val.w;
    }
    acc.x += __shfl_xor_sync(~0u, acc.x, 16);
    acc.y += __shfl_xor_sync(~0u, acc.y, 16);
    acc.z += __shfl_xor_sync(~0u, acc.z, 16);
    acc.w += __shfl_xor_sync(~0u, acc.w, 16);
    if (half == 0) {
        int d = dl * 4;
        float4 b4 = *reinterpret_cast<const float4*>(&bias[h*HID + d]);
        float4 o4 = make_float4(acc.x + b4.x, acc.y + b4.y, acc.z + b4.z, acc.w + b4.w);
        if (do_relu) {
            o4.x = fmaxf(o4.x, 0.f); o4.y = fmaxf(o4.y, 0.f);
            o4.z = fmaxf(o4.z, 0.f); o4.w = fmaxf(o4.w, 0.f);
        }
        *reinterpret_cast<float4*>(&out[((long)v * nh + h) * HID + d]) = o4;
    }
}

// ---------------- scores, labels, per-row loss ----------------
__global__ void score_kernel(const float* __restrict__ h2, const int* __restrict__ uid,
                             const int* __restrict__ iid, float* __restrict__ out) {
    int i = blockIdx.x;
    int d = threadIdx.x;
    float su = h2[(long)uid[i] * HID + d];
    float si = h2[(long)iid[i] * HID + d];
    float sc = su * si;
    out[1 + i*BATCH + d] = sc;
    out[1 + BATCH*BATCH + i*BATCH + d] = (i == d) ? 1.f : 0.f;

    __shared__ float buf[BATCH];
    __shared__ float diag;
    if (d == i) diag = sc;
    buf[d] = sc;
    __syncthreads();
    for (int st = 32; st > 0; st >>= 1) {
        if (d < st) buf[d] = fmaxf(buf[d], buf[d + st]);
        __syncthreads();
    }
    float mx = buf[0];
    __syncthreads();
    buf[d] = expf(sc - mx);
    __syncthreads();
    for (int st = 32; st > 0; st >>= 1) {
        if (d < st) buf[d] += buf[d + st];
        __syncthreads();
    }
    if (d == 0) {
        float lse = mx + logf(buf[0]);
        g_loss[i] = lse - diag;
    }
}

__global__ void finalize_kernel(float* __restrict__ out) {
    if (threadIdx.x == 0) {
        float s = 0.f;
        for (int i = 0; i < BATCH; i++) s += g_loss[i];
        out[0] = s / (float)BATCH;
    }
}

// ---------------- launcher ----------------
extern "C" void kernel_launch(void* const* d_in, const int* in_sizes, int n_in,
                              void* d_out, int out_size) {
    const int*   feat_ids = (const int*)  d_in[0];
    const int*   src      = (const int*)  d_in[1];
    const int*   user_ids = (const int*)  d_in[3];
    const int*   item_ids = (const int*)  d_in[4];
    const float* emb      = (const float*)d_in[5];
    const float* W1       = (const float*)d_in[6];
    const float* a_l1     = (const float*)d_in[7];
    const float* a_r1     = (const float*)d_in[8];
    const float* b1       = (const float*)d_in[9];
    const float* W2       = (const float*)d_in[10];
    const float* a_l2     = (const float*)d_in[11];
    const float* a_r2     = (const float*)d_in[12];
    const float* b2       = (const float*)d_in[13];
    float* out = (float*)d_out;

    float *f1, *el1, *er1, *h1, *f2, *el2, *er2, *h2;
    cudaGetSymbolAddress((void**)&f1,  g_f1);
    cudaGetSymbolAddress((void**)&el1, g_el1);
    cudaGetSymbolAddress((void**)&er1, g_er1);
    cudaGetSymbolAddress((void**)&h1,  g_h1);
    cudaGetSymbolAddress((void**)&f2,  g_f2);
    cudaGetSymbolAddress((void**)&el2, g_el2);
    cudaGetSymbolAddress((void**)&er2, g_er2);
    cudaGetSymbolAddress((void**)&h2,  g_h2);

    // layer 1: f1 = emb[feat_ids] @ W1 (50000x128x256) + fused el1/er1
    gemm_fused<64,256,16,8,8,4><<<(NND+63)/64, 256>>>(
        emb, feat_ids, W1, a_l1, a_r1, f1, el1, er1, NND, IN_F);
    agg_kernel<<<(NND*NH)/8, 256>>>(f1, el1, er1, b1, src, h1, NH, 1);

    // layer 2: f2 = h1 @ W2 (50000x256x64) + fused el2/er2
    gemm_fused<128,64,32,8,8,1><<<(NND+127)/128, 128>>>(
        h1, nullptr, W2, a_l2, a_r2, f2, el2, er2, NND, NH*HID);
    agg_kernel<<<NND/8, 256>>>(f2, el2, er2, b2, src, h2, 1, 0);

    score_kernel<<<BATCH, BATCH>>>(h2, user_ids, item_ids, out);
    finalize_kernel<<<1, 32>>>(out);
}

// round 4
// speedup vs baseline: 1.5653x; 1.1034x over previous
#include <cuda_runtime.h>
#include <cuda_fp16.h>

// ---------------- problem constants ----------------
#define NND   50000
#define DEG   16
#define IN_F  128
#define HID   64
#define NH    4
#define BATCH 64

typedef unsigned long long ull;

// ---------------- scratch ----------------
__device__ __half g_f1h[NND*NH*HID];   // fp16 gather operand, layer 1
__device__ float  g_el1[NND*NH];
__device__ float  g_er1[NND*NH];
__device__ float  g_h1 [NND*NH*HID];   // fp32: GEMM2 input
__device__ __half g_f2h[NND*HID];      // fp16 gather operand, layer 2
__device__ float  g_el2[NND];
__device__ float  g_er2[NND];
__device__ float  g_h2 [NND*HID];
__device__ float  g_loss[BATCH];

// ---------------- packed f32x2 helpers (sm_103a FFMA2 pipe) ----------------
__device__ __forceinline__ ull pack_dup(float x) {
    ull r; asm("mov.b64 %0, {%1, %1};" : "=l"(r) : "f"(x)); return r;
}
__device__ __forceinline__ void ffma2(ull& acc, ull a, ull b) {
    asm("fma.rn.f32x2 %0, %1, %2, %0;" : "+l"(acc) : "l"(a), "l"(b));
}
__device__ __forceinline__ float2 unpack2(ull v) {
    float2 f; asm("mov.b64 {%0, %1}, %2;" : "=f"(f.x), "=f"(f.y) : "l"(v)); return f;
}

// ---------------- GEMM (full-width N) with fused attention dots ----------------
// Ch[m, 0:BN] = half(A[gidx[m], :] @ B) ; el/er[m,h] = fp32 head dots
template<int BM,int BN,int BK,int TM,int TN,int NHh>
__global__ __launch_bounds__((BM/TM)*(BN/TN))
void gemm_fused(const float* __restrict__ A, const int* __restrict__ gidx,
                const float* __restrict__ B,
                const float* __restrict__ al, const float* __restrict__ ar,
                __half* __restrict__ Ch, float* __restrict__ el, float* __restrict__ er,
                int M, int K) {
    constexpr int NT = (BM/TM)*(BN/TN);
    __shared__ float As[BK][BM];
    __shared__ float Bs[BK][BN];
    const int tid = threadIdx.x;
    const int tx  = tid % (BN/TN);
    const int ty  = tid / (BN/TN);
    const int m0  = blockIdx.x * BM;

    constexpr int A_F4 = BM*BK/4;
    constexpr int A_IT = A_F4 / NT;
    static_assert(A_IT >= 1 && A_F4 % NT == 0, "A tiling");
    long arow[A_IT];
    #pragma unroll
    for (int r = 0; r < A_IT; r++) {
        int idx = tid + r*NT;
        int mA  = idx / (BK/4);
        int gm  = m0 + mA;
        int row = (gm < M) ? (gidx ? gidx[gm] : gm) : 0;
        arow[r] = (long)row * K;
    }
    constexpr int B_F4 = BK*BN/4;
    constexpr int B_IT = B_F4 / NT;
    static_assert(B_IT >= 1 && B_F4 % NT == 0, "B tiling");

    ull acc2[TM/2][TN];
    #pragma unroll
    for (int i = 0; i < TM/2; i++)
        #pragma unroll
        for (int j = 0; j < TN; j++) acc2[i][j] = 0ull;

    for (int k0 = 0; k0 < K; k0 += BK) {
        #pragma unroll
        for (int r = 0; r < A_IT; r++) {
            int idx = tid + r*NT;
            int mA  = idx / (BK/4);
            int kq  = idx % (BK/4);
            float4 v = *reinterpret_cast<const float4*>(A + arow[r] + k0 + kq*4);
            As[kq*4+0][mA] = v.x;
            As[kq*4+1][mA] = v.y;
            As[kq*4+2][mA] = v.z;
            As[kq*4+3][mA] = v.w;
        }
        #pragma unroll
        for (int r = 0; r < B_IT; r++) {
            int idx = tid + r*NT;
            int kB  = idx / (BN/4);
            int nq  = idx % (BN/4);
            float4 v = *reinterpret_cast<const float4*>(B + (long)(k0+kB)*BN + nq*4);
            *reinterpret_cast<float4*>(&Bs[kB][nq*4]) = v;
        }
        __syncthreads();
        #pragma unroll
        for (int k = 0; k < BK; k++) {
            ull a2[TM/2];
            const ull* ap = reinterpret_cast<const ull*>(&As[k][ty*TM]);
            #pragma unroll
            for (int i = 0; i < TM/2; i++) a2[i] = ap[i];
            ull b2[TN];
            #pragma unroll
            for (int j = 0; j < TN; j++) b2[j] = pack_dup(Bs[k][tx*TN + j]);
            #pragma unroll
            for (int i = 0; i < TM/2; i++)
                #pragma unroll
                for (int j = 0; j < TN; j++) ffma2(acc2[i][j], a2[i], b2[j]);
        }
        __syncthreads();
    }

    float acc[TM][TN];
    #pragma unroll
    for (int i = 0; i < TM/2; i++)
        #pragma unroll
        for (int j = 0; j < TN; j++) {
            float2 p = unpack2(acc2[i][j]);
            acc[2*i  ][j] = p.x;
            acc[2*i+1][j] = p.y;
        }

    float alr[TN], arr[TN];
    #pragma unroll
    for (int j = 0; j < TN; j++) { int n = tx*TN + j; alr[j] = al[n]; arr[j] = ar[n]; }

    #pragma unroll
    for (int i = 0; i < TM; i++) {
        int gm = m0 + ty*TM + i;
        float sl = 0.f, sr = 0.f;
        #pragma unroll
        for (int j = 0; j < TN; j++) { sl += acc[i][j]*alr[j]; sr += acc[i][j]*arr[j]; }
        #pragma unroll
        for (int o = 1; o < 8; o <<= 1) {
            sl += __shfl_xor_sync(~0u, sl, o);
            sr += __shfl_xor_sync(~0u, sr, o);
        }
        if (gm < M) {
            // convert 8 fp32 -> 4 half2, one 16B store
            static_assert(TN == 8, "epilogue assumes TN=8");
            __half2 p0 = __floats2half2_rn(acc[i][0], acc[i][1]);
            __half2 p1 = __floats2half2_rn(acc[i][2], acc[i][3]);
            __half2 p2 = __floats2half2_rn(acc[i][4], acc[i][5]);
            __half2 p3 = __floats2half2_rn(acc[i][6], acc[i][7]);
            uint4 w;
            w.x = *reinterpret_cast<unsigned*>(&p0);
            w.y = *reinterpret_cast<unsigned*>(&p1);
            w.z = *reinterpret_cast<unsigned*>(&p2);
            w.w = *reinterpret_cast<unsigned*>(&p3);
            *reinterpret_cast<uint4*>(&Ch[(long)gm*BN + tx*TN]) = w;
            if ((tx & 7) == 0) {
                int h = tx >> 3;
                el[(long)gm*NHh + h] = sl;
                er[(long)gm*NHh + h] = sr;
            }
        }
    }
}

// ------------- segment-softmax + fp16 weighted aggregation (2 edges/iter) -----
__global__ void agg_kernel(const __half* __restrict__ f, const float* __restrict__ el,
                           const float* __restrict__ er, const float* __restrict__ bias,
                           const int* __restrict__ src, float* __restrict__ out,
                           int nh, int do_relu) {
    int gw   = (blockIdx.x * blockDim.x + threadIdx.x) >> 5;
    int lane = threadIdx.x & 31;
    if (gw >= NND * nh) return;
    int v = gw / nh, h = gw - v*nh;

    float erv = er[(long)v * nh + h];
    int   s   = 0;
    float e   = -1e30f;
    if (lane < DEG) {
        s = src[v * DEG + lane];
        float x = el[(long)s * nh + h] + erv;
        e = x > 0.f ? x : 0.2f * x;   // leaky_relu(0.2)
    }
    float m = e;
    #pragma unroll
    for (int o = 8; o > 0; o >>= 1) m = fmaxf(m, __shfl_xor_sync(~0u, m, o, 16));
    float ex = (lane < DEG) ? __expf(e - m) : 0.f;
    float sm = ex;
    #pragma unroll
    for (int o = 8; o > 0; o >>= 1) sm += __shfl_xor_sync(~0u, sm, o, 16);
    float alpha = ex / sm;            // valid on lanes 0..15

    // lanes 0..15 = dims [0..63] (4 per lane); half = lane>>4 picks edge parity
    int half_ = lane >> 4;
    int dl    = lane & 15;
    float4 acc = make_float4(0.f, 0.f, 0.f, 0.f);
    #pragma unroll
    for (int j = 0; j < DEG/2; j++) {
        int   eidx = 2*j + half_;
        int   sj = __shfl_sync(~0u, s,     eidx);
        float aj = __shfl_sync(~0u, alpha, eidx);
        uint2 raw = *reinterpret_cast<const uint2*>(
            f + ((long)sj * nh + h) * HID + dl * 4);
        float2 f0 = __half22float2(*reinterpret_cast<__half2*>(&raw.x));
        float2 f1 = __half22float2(*reinterpret_cast<__half2*>(&raw.y));
        acc.x += aj * f0.x;
        acc.y += aj * f0.y;
        acc.z += aj * f1.x;
        acc.w += aj * f1.y;
    }
    acc.x += __shfl_xor_sync(~0u, acc.x, 16);
    acc.y += __shfl_xor_sync(~0u, acc.y, 16);
    acc.z += __shfl_xor_sync(~0u, acc.z, 16);
    acc.w += __shfl_xor_sync(~0u, acc.w, 16);
    if (half_ == 0) {
        int d = dl * 4;
        float4 b4 = *reinterpret_cast<const float4*>(&bias[h*HID + d]);
        float4 o4 = make_float4(acc.x + b4.x, acc.y + b4.y, acc.z + b4.z, acc.w + b4.w);
        if (do_relu) {
            o4.x = fmaxf(o4.x, 0.f); o4.y = fmaxf(o4.y, 0.f);
            o4.z = fmaxf(o4.z, 0.f); o4.w = fmaxf(o4.w, 0.f);
        }
        *reinterpret_cast<float4*>(&out[((long)v * nh + h) * HID + d]) = o4;
    }
}

// ---------------- scores, labels, per-row loss ----------------
__global__ void score_kernel(const float* __restrict__ h2, const int* __restrict__ uid,
                             const int* __restrict__ iid, float* __restrict__ out) {
    int i = blockIdx.x;
    int d = threadIdx.x;
    float su = h2[(long)uid[i] * HID + d];
    float si = h2[(long)iid[i] * HID + d];
    float sc = su * si;
    out[1 + i*BATCH + d] = sc;
    out[1 + BATCH*BATCH + i*BATCH + d] = (i == d) ? 1.f : 0.f;

    __shared__ float buf[BATCH];
    __shared__ float diag;
    if (d == i) diag = sc;
    buf[d] = sc;
    __syncthreads();
    for (int st = 32; st > 0; st >>= 1) {
        if (d < st) buf[d] = fmaxf(buf[d], buf[d + st]);
        __syncthreads();
    }
    float mx = buf[0];
    __syncthreads();
    buf[d] = expf(sc - mx);
    __syncthreads();
    for (int st = 32; st > 0; st >>= 1) {
        if (d < st) buf[d] += buf[d + st];
        __syncthreads();
    }
    if (d == 0) {
        float lse = mx + logf(buf[0]);
        g_loss[i] = lse - diag;
    }
}

__global__ void finalize_kernel(float* __restrict__ out) {
    if (threadIdx.x == 0) {
        float s = 0.f;
        for (int i = 0; i < BATCH; i++) s += g_loss[i];
        out[0] = s / (float)BATCH;
    }
}

// ---------------- launcher ----------------
extern "C" void kernel_launch(void* const* d_in, const int* in_sizes, int n_in,
                              void* d_out, int out_size) {
    const int*   feat_ids = (const int*)  d_in[0];
    const int*   src      = (const int*)  d_in[1];
    const int*   user_ids = (const int*)  d_in[3];
    const int*   item_ids = (const int*)  d_in[4];
    const float* emb      = (const float*)d_in[5];
    const float* W1       = (const float*)d_in[6];
    const float* a_l1     = (const float*)d_in[7];
    const float* a_r1     = (const float*)d_in[8];
    const float* b1       = (const float*)d_in[9];
    const float* W2       = (const float*)d_in[10];
    const float* a_l2     = (const float*)d_in[11];
    const float* a_r2     = (const float*)d_in[12];
    const float* b2       = (const float*)d_in[13];
    float* out = (float*)d_out;

    __half *f1h, *f2h;
    float *el1, *er1, *h1, *el2, *er2, *h2;
    cudaGetSymbolAddress((void**)&f1h, g_f1h);
    cudaGetSymbolAddress((void**)&el1, g_el1);
    cudaGetSymbolAddress((void**)&er1, g_er1);
    cudaGetSymbolAddress((void**)&h1,  g_h1);
    cudaGetSymbolAddress((void**)&f2h, g_f2h);
    cudaGetSymbolAddress((void**)&el2, g_el2);
    cudaGetSymbolAddress((void**)&er2, g_er2);
    cudaGetSymbolAddress((void**)&h2,  g_h2);

    // layer 1: f1 = emb[feat_ids] @ W1 (50000x128x256) + fused el1/er1, fp16 out
    gemm_fused<64,256,16,8,8,4><<<(NND+63)/64, 256>>>(
        emb, feat_ids, W1, a_l1, a_r1, f1h, el1, er1, NND, IN_F);
    agg_kernel<<<(NND*NH)/8, 256>>>(f1h, el1, er1, b1, src, h1, NH, 1);

    // layer 2: f2 = h1 @ W2 (50000x256x64) + fused el2/er2, fp16 out
    gemm_fused<128,64,32,8,8,1><<<(NND+127)/128, 128>>>(
        h1, nullptr, W2, a_l2, a_r2, f2h, el2, er2, NND, NH*HID);
    agg_kernel<<<NND/8, 256>>>(f2h, el2, er2, b2, src, h2, 1, 0);

    score_kernel<<<BATCH, BATCH>>>(h2, user_ids, item_ids, out);
    finalize_kernel<<<1, 32>>>(out);
}

// round 5
// speedup vs baseline: 1.6440x; 1.0503x over previous
#include <cuda_runtime.h>
#include <cuda_fp16.h>

// ---------------- problem constants ----------------
#define NND   50000
#define DEG   16
#define IN_F  128
#define HID   64
#define NH    4
#define BATCH 64

typedef unsigned long long ull;

// ---------------- scratch ----------------
__device__ __half g_f1h[NND*NH*HID];
__device__ float  g_el1[NND*NH];
__device__ float  g_er1[NND*NH];
__device__ float  g_h1 [NND*NH*HID];
__device__ __half g_f2h[NND*HID];
__device__ float  g_el2[NND];
__device__ float  g_er2[NND];
__device__ float  g_h2 [NND*HID];
__device__ float  g_loss[BATCH];

// ---------------- packed f32x2 helpers ----------------
__device__ __forceinline__ ull pack_dup(float x) {
    ull r; asm("mov.b64 %0, {%1, %1};" : "=l"(r) : "f"(x)); return r;
}
__device__ __forceinline__ void ffma2(ull& acc, ull a, ull b) {
    asm("fma.rn.f32x2 %0, %1, %2, %0;" : "+l"(acc) : "l"(a), "l"(b));
}
__device__ __forceinline__ float2 unpack2(ull v) {
    float2 f; asm("mov.b64 {%0, %1}, %2;" : "=f"(f.x), "=f"(f.y) : "l"(v)); return f;
}

// ---------------- GEMM with 2-D warp tiling + fused attention dots ----------
// Ch[m, 0:BN] = half(A[gidx[m], :] @ B) ; el/er[m,h] = fp32 head dots
// Warp tile = 32(M) x 64(N); lanes = 4(M) x 8(N); thread tile 8x8.
template<int BM,int BN,int BK,int NHh>
__global__ __launch_bounds__((BM/8)*(BN/8))
void gemm_fused(const float* __restrict__ A, const int* __restrict__ gidx,
                const float* __restrict__ B,
                const float* __restrict__ al, const float* __restrict__ ar,
                __half* __restrict__ Ch, float* __restrict__ el, float* __restrict__ er,
                int M, int K) {
    constexpr int TM = 8, TN = 8;
    constexpr int NT = (BM/TM)*(BN/TN);
    constexpr int NWARP = NT/32;
    constexpr int WN = BN/64;            // warps along N
    constexpr int WM = NWARP/WN;         // warps along M
    static_assert(WM*32 == BM && WN*64 == BN, "warp tiling");
    __shared__ float As[BK][BM];
    __shared__ float Bs[BK][BN];
    const int tid  = threadIdx.x;
    const int warp = tid >> 5;
    const int lane = tid & 31;
    const int wm = warp % WM, wn = warp / WM;
    const int lr = lane >> 3, lc = lane & 7;
    const int ty = wm*4 + lr;            // row-tile index   (0..BM/8-1)
    const int tx = wn*8 + lc;            // col-tile index   (0..BN/8-1)
    const int m0 = blockIdx.x * BM;

    constexpr int A_F4 = BM*BK/4;
    constexpr int A_IT = A_F4 / NT;
    static_assert(A_IT >= 1 && A_F4 % NT == 0, "A tiling");
    long arow[A_IT];
    #pragma unroll
    for (int r = 0; r < A_IT; r++) {
        int idx = tid + r*NT;
        int mA  = idx / (BK/4);
        int gm  = m0 + mA;
        int row = (gm < M) ? (gidx ? gidx[gm] : gm) : 0;
        arow[r] = (long)row * K;
    }
    constexpr int B_F4 = BK*BN/4;
    constexpr int B_IT = B_F4 / NT;
    static_assert(B_IT >= 1 && B_F4 % NT == 0, "B tiling");

    ull acc2[TM/2][TN];
    #pragma unroll
    for (int i = 0; i < TM/2; i++)
        #pragma unroll
        for (int j = 0; j < TN; j++) acc2[i][j] = 0ull;

    for (int k0 = 0; k0 < K; k0 += BK) {
        #pragma unroll
        for (int r = 0; r < A_IT; r++) {
            int idx = tid + r*NT;
            int mA  = idx / (BK/4);
            int kq  = idx % (BK/4);
            float4 v = *reinterpret_cast<const float4*>(A + arow[r] + k0 + kq*4);
            As[kq*4+0][mA] = v.x;
            As[kq*4+1][mA] = v.y;
            As[kq*4+2][mA] = v.z;
            As[kq*4+3][mA] = v.w;
        }
        #pragma unroll
        for (int r = 0; r < B_IT; r++) {
            int idx = tid + r*NT;
            int kB  = idx / (BN/4);
            int nq  = idx % (BN/4);
            float4 v = *reinterpret_cast<const float4*>(B + (long)(k0+kB)*BN + nq*4);
            *reinterpret_cast<float4*>(&Bs[kB][nq*4]) = v;
        }
        __syncthreads();
        #pragma unroll
        for (int k = 0; k < BK; k++) {
            // A fragment: 4 x LDS.64 (broadcast across 8 lanes sharing lr)
            ull a2[TM/2];
            const ull* ap = reinterpret_cast<const ull*>(&As[k][ty*TM]);
            #pragma unroll
            for (int i = 0; i < TM/2; i++) a2[i] = ap[i];
            // B fragment: 2 x LDS.128, then dup-pack
            float4 blo = *reinterpret_cast<const float4*>(&Bs[k][tx*TN]);
            float4 bhi = *reinterpret_cast<const float4*>(&Bs[k][tx*TN+4]);
            ull b2[TN];
            b2[0]=pack_dup(blo.x); b2[1]=pack_dup(blo.y);
            b2[2]=pack_dup(blo.z); b2[3]=pack_dup(blo.w);
            b2[4]=pack_dup(bhi.x); b2[5]=pack_dup(bhi.y);
            b2[6]=pack_dup(bhi.z); b2[7]=pack_dup(bhi.w);
            #pragma unroll
            for (int i = 0; i < TM/2; i++)
                #pragma unroll
                for (int j = 0; j < TN; j++) ffma2(acc2[i][j], a2[i], b2[j]);
        }
        __syncthreads();
    }

    float acc[TM][TN];
    #pragma unroll
    for (int i = 0; i < TM/2; i++)
        #pragma unroll
        for (int j = 0; j < TN; j++) {
            float2 p = unpack2(acc2[i][j]);
            acc[2*i  ][j] = p.x;
            acc[2*i+1][j] = p.y;
        }

    float alr[TN], arr[TN];
    #pragma unroll
    for (int j = 0; j < TN; j++) { int n = tx*TN + j; alr[j] = al[n]; arr[j] = ar[n]; }

    #pragma unroll
    for (int i = 0; i < TM; i++) {
        int gm = m0 + ty*TM + i;
        float sl = 0.f, sr = 0.f;
        #pragma unroll
        for (int j = 0; j < TN; j++) { sl += acc[i][j]*alr[j]; sr += acc[i][j]*arr[j]; }
        #pragma unroll
        for (int o = 1; o < 8; o <<= 1) {       // reduce across the 8 lanes of one head
            sl += __shfl_xor_sync(~0u, sl, o);
            sr += __shfl_xor_sync(~0u, sr, o);
        }
        if (gm < M) {
            __half2 p0 = __floats2half2_rn(acc[i][0], acc[i][1]);
            __half2 p1 = __floats2half2_rn(acc[i][2], acc[i][3]);
            __half2 p2 = __floats2half2_rn(acc[i][4], acc[i][5]);
            __half2 p3 = __floats2half2_rn(acc[i][6], acc[i][7]);
            uint4 w;
            w.x = *reinterpret_cast<unsigned*>(&p0);
            w.y = *reinterpret_cast<unsigned*>(&p1);
            w.z = *reinterpret_cast<unsigned*>(&p2);
            w.w = *reinterpret_cast<unsigned*>(&p3);
            *reinterpret_cast<uint4*>(&Ch[(long)gm*BN + tx*TN]) = w;
            if (lc == 0) {
                el[(long)gm*NHh + wn] = sl;
                er[(long)gm*NHh + wn] = sr;
            }
        }
    }
}

// ------------- segment-softmax + fp16 weighted aggregation -----------------
template<int NHh, bool RELU>
__global__ void agg_kernel(const __half* __restrict__ f, const float* __restrict__ el,
                           const float* __restrict__ er, const float* __restrict__ bias,
                           const int* __restrict__ src, float* __restrict__ out) {
    int gw   = (blockIdx.x * blockDim.x + threadIdx.x) >> 5;
    int lane = threadIdx.x & 31;
    if (gw >= NND * NHh) return;
    int v = gw / NHh, h = gw - v*NHh;

    float erv = er[v*NHh + h];
    int   off = 0;
    float e   = -1e30f;
    if (lane < DEG) {
        int s = src[v * DEG + lane];
        off = s * (NHh*HID*2);                 // byte offset of node row (32-bit)
        float x = el[s*NHh + h] + erv;
        e = x > 0.f ? x : 0.2f * x;            // leaky_relu(0.2)
    }
    float m = e;
    #pragma unroll
    for (int o = 8; o > 0; o >>= 1) m = fmaxf(m, __shfl_xor_sync(~0u, m, o, 16));
    float ex = (lane < DEG) ? __expf(e - m) : 0.f;
    float sm = ex;
    #pragma unroll
    for (int o = 8; o > 0; o >>= 1) sm += __shfl_xor_sync(~0u, sm, o, 16);
    float alpha = ex / sm;                     // valid on lanes 0..15

    int half_ = lane >> 4;
    int dl    = lane & 15;
    const char* base = reinterpret_cast<const char*>(f) + h*(HID*2) + dl*8;
    float4 acc = make_float4(0.f, 0.f, 0.f, 0.f);
    #pragma unroll
    for (int j = 0; j < DEG/2; j++) {
        int   eidx = 2*j + half_;
        int   oj = __shfl_sync(~0u, off,   eidx);
        float aj = __shfl_sync(~0u, alpha, eidx);
        uint2 raw = *reinterpret_cast<const uint2*>(base + oj);
        float2 f0 = __half22float2(*reinterpret_cast<__half2*>(&raw.x));
        float2 f1 = __half22float2(*reinterpret_cast<__half2*>(&raw.y));
        acc.x += aj * f0.x;
        acc.y += aj * f0.y;
        acc.z += aj * f1.x;
        acc.w += aj * f1.y;
    }
    acc.x += __shfl_xor_sync(~0u, acc.x, 16);
    acc.y += __shfl_xor_sync(~0u, acc.y, 16);
    acc.z += __shfl_xor_sync(~0u, acc.z, 16);
    acc.w += __shfl_xor_sync(~0u, acc.w, 16);
    if (half_ == 0) {
        int d = dl * 4;
        float4 b4 = *reinterpret_cast<const float4*>(&bias[h*HID + d]);
        float4 o4 = make_float4(acc.x + b4.x, acc.y + b4.y, acc.z + b4.z, acc.w + b4.w);
        if (RELU) {
            o4.x = fmaxf(o4.x, 0.f); o4.y = fmaxf(o4.y, 0.f);
            o4.z = fmaxf(o4.z, 0.f); o4.w = fmaxf(o4.w, 0.f);
        }
        *reinterpret_cast<float4*>(&out[((long)v * NHh + h) * HID + d]) = o4;
    }
}

// ---------------- scores, labels, per-row loss ----------------
__global__ void score_kernel(const float* __restrict__ h2, const int* __restrict__ uid,
                             const int* __restrict__ iid, float* __restrict__ out) {
    int i = blockIdx.x;
    int d = threadIdx.x;
    float su = h2[(long)uid[i] * HID + d];
    float si = h2[(long)iid[i] * HID + d];
    float sc = su * si;
    out[1 + i*BATCH + d] = sc;
    out[1 + BATCH*BATCH + i*BATCH + d] = (i == d) ? 1.f : 0.f;

    __shared__ float buf[BATCH];
    __shared__ float diag;
    if (d == i) diag = sc;
    buf[d] = sc;
    __syncthreads();
    for (int st = 32; st > 0; st >>= 1) {
        if (d < st) buf[d] = fmaxf(buf[d], buf[d + st]);
        __syncthreads();
    }
    float mx = buf[0];
    __syncthreads();
    buf[d] = expf(sc - mx);
    __syncthreads();
    for (int st = 32; st > 0; st >>= 1) {
        if (d < st) buf[d] += buf[d + st];
        __syncthreads();
    }
    if (d == 0) {
        float lse = mx + logf(buf[0]);
        g_loss[i] = lse - diag;
    }
}

__global__ void finalize_kernel(float* __restrict__ out) {
    if (threadIdx.x == 0) {
        float s = 0.f;
        for (int i = 0; i < BATCH; i++) s += g_loss[i];
        out[0] = s / (float)BATCH;
    }
}

// ---------------- launcher ----------------
extern "C" void kernel_launch(void* const* d_in, const int* in_sizes, int n_in,
                              void* d_out, int out_size) {
    const int*   feat_ids = (const int*)  d_in[0];
    const int*   src      = (const int*)  d_in[1];
    const int*   user_ids = (const int*)  d_in[3];
    const int*   item_ids = (const int*)  d_in[4];
    const float* emb      = (const float*)d_in[5];
    const float* W1       = (const float*)d_in[6];
    const float* a_l1     = (const float*)d_in[7];
    const float* a_r1     = (const float*)d_in[8];
    const float* b1       = (const float*)d_in[9];
    const float* W2       = (const float*)d_in[10];
    const float* a_l2     = (const float*)d_in[11];
    const float* a_r2     = (const float*)d_in[12];
    const float* b2       = (const float*)d_in[13];
    float* out = (float*)d_out;

    __half *f1h, *f2h;
    float *el1, *er1, *h1, *el2, *er2, *h2;
    cudaGetSymbolAddress((void**)&f1h, g_f1h);
    cudaGetSymbolAddress((void**)&el1, g_el1);
    cudaGetSymbolAddress((void**)&er1, g_er1);
    cudaGetSymbolAddress((void**)&h1,  g_h1);
    cudaGetSymbolAddress((void**)&f2h, g_f2h);
    cudaGetSymbolAddress((void**)&el2, g_el2);
    cudaGetSymbolAddress((void**)&er2, g_er2);
    cudaGetSymbolAddress((void**)&h2,  g_h2);

    // layer 1: f1 = emb[feat_ids] @ W1 (50000x128x256) + fused el1/er1, fp16 out
    gemm_fused<64,256,16,4><<<(NND+63)/64, 256>>>(
        emb, feat_ids, W1, a_l1, a_r1, f1h, el1, er1, NND, IN_F);
    agg_kernel<NH,true><<<(NND*NH)/8, 256>>>(f1h, el1, er1, b1, src, h1);

    // layer 2: f2 = h1 @ W2 (50000x256x64) + fused el2/er2, fp16 out
    gemm_fused<128,64,32,1><<<(NND+127)/128, 128>>>(
        h1, nullptr, W2, a_l2, a_r2, f2h, el2, er2, NND, NH*HID);
    agg_kernel<1,false><<<NND/8, 256>>>(f2h, el2, er2, b2, src, h2);

    score_kernel<<<BATCH, BATCH>>>(h2, user_ids, item_ids, out);
    finalize_kernel<<<1, 32>>>(out);
}